// round 2
// baseline (speedup 1.0000x reference)
#include <cuda_runtime.h>
#include <math.h>
#include <stdint.h>

#define MAXN 100000
#define MAXE 1600000
#define D 128

// ---------------- device scratch (no allocations allowed) ----------------
__device__ float g_h[(size_t)MAXN * D];   // projected features of current layer
__device__ float g_x[(size_t)MAXN * D];   // layer activations (ping buffer)
__device__ float g_as[MAXN];              // alpha_src per node
__device__ float g_ad[MAXN];              // alpha_dst per node
__device__ int   g_csr_src[MAXE];         // src ids sorted by dst
__device__ int   g_rowptr[MAXN + 1];
__device__ int   g_cursor[MAXN];
__device__ int   g_deg[MAXN];
__device__ float g_bnsum[D];
__device__ float g_bnsq[D];
__device__ float g_scale[D];
__device__ float g_shift[D];
__device__ int   g_flag;                  // 1 => edge_index stored as int32

// ---------------- init / dtype detection ----------------
__global__ void zero_kernel(int n) {
    int i = blockIdx.x * blockDim.x + threadIdx.x;
    if (i < n) g_deg[i] = 0;
    if (i < D) { g_bnsum[i] = 0.f; g_bnsq[i] = 0.f; }
}

// edge_index layout detection: read first 512 32-bit words. If int64 (nonneg
// values < 2^31), every odd word (high half) is 0. If int32 random node ids,
// P(all 256 odd words == 0) ~ (1e-5)^256 == never.
__global__ void detect_kernel(const unsigned* __restrict__ ei) {
    __shared__ int found;
    if (threadIdx.x == 0) found = 0;
    __syncthreads();
    unsigned w = ei[2 * threadIdx.x + 1];
    if (w != 0u) found = 1;
    __syncthreads();
    if (threadIdx.x == 0) g_flag = found;   // nonzero odd word => int32
}

__device__ __forceinline__ int load_idx(const void* ei, long long pos) {
    if (g_flag) return ((const int*)ei)[pos];
    return (int)((const long long*)ei)[pos];
}

__global__ void count_kernel(const void* __restrict__ ei, int E) {
    int i = blockIdx.x * blockDim.x + threadIdx.x;
    if (i >= E) return;
    int dst = load_idx(ei, (long long)E + i);
    atomicAdd(&g_deg[dst], 1);
}

// single-block exclusive scan of g_deg -> g_rowptr / g_cursor
__global__ void scan_kernel(int n) {
    __shared__ int wsum[32];
    __shared__ int carry;
    int tid = threadIdx.x, lane = tid & 31, wid = tid >> 5;
    if (tid == 0) carry = 0;
    __syncthreads();
    for (int base = 0; base < n; base += 1024) {
        int i = base + tid;
        int v = (i < n) ? g_deg[i] : 0;
        int incl = v;
        #pragma unroll
        for (int o = 1; o < 32; o <<= 1) {
            int t = __shfl_up_sync(0xffffffffu, incl, o);
            if (lane >= o) incl += t;
        }
        if (lane == 31) wsum[wid] = incl;
        __syncthreads();
        if (wid == 0) {
            int s = wsum[lane];
            #pragma unroll
            for (int o = 1; o < 32; o <<= 1) {
                int t = __shfl_up_sync(0xffffffffu, s, o);
                if (lane >= o) s += t;
            }
            wsum[lane] = s;
        }
        __syncthreads();
        int woff = (wid > 0) ? wsum[wid - 1] : 0;
        int excl = carry + woff + incl - v;
        if (i < n) { g_rowptr[i] = excl; g_cursor[i] = excl; }
        __syncthreads();
        if (tid == 0) carry += wsum[31];
        __syncthreads();
    }
    if (threadIdx.x == 0) g_rowptr[n] = carry;
}

__global__ void scatter_kernel(const void* __restrict__ ei, int E) {
    int i = blockIdx.x * blockDim.x + threadIdx.x;
    if (i >= E) return;
    int src = load_idx(ei, i);
    int dst = load_idx(ei, (long long)E + i);
    int pos = atomicAdd(&g_cursor[dst], 1);
    g_csr_src[pos] = src;
}

// ---------------- GEMM: h = f(x) @ W, fused BN+ReLU on load, fused alpha dots ----------------
// block = 64 rows x 128 cols, 256 threads (8 warps x 8 rows each, lane owns 4 cols).
// K is processed in two 64-wide chunks so static smem fits in 48 KB:
//   sW: [64 k][128 cols] = 32 KB, sX: [64 rows][64 k] = 16 KB.
__global__ void __launch_bounds__(256)
gemm_kernel(const float* __restrict__ xext, int use_ext,
            const float* __restrict__ W,
            const float* __restrict__ avs, const float* __restrict__ avd,
            int use_bn, int n) {
    __shared__ float4 sW4[64 * 32];   // 32 KB
    __shared__ float4 sX4[64 * 16];   // 16 KB
    const float* xsrc = use_ext ? xext : g_x;
    int tid = threadIdx.x;
    int row0 = blockIdx.x * 64;
    int warp = tid >> 5, lane = tid & 31;

    const float4* W4 = (const float4*)W;
    const float4* X4 = (const float4*)xsrc;

    float4 acc[8];
    #pragma unroll
    for (int r = 0; r < 8; r++) acc[r] = make_float4(0.f, 0.f, 0.f, 0.f);

    #pragma unroll
    for (int kc = 0; kc < 2; kc++) {
        // stage W rows [kc*64, kc*64+64)
        #pragma unroll 4
        for (int i = tid; i < 64 * 32; i += 256) sW4[i] = W4[kc * 64 * 32 + i];
        // stage X tile (rows row0..row0+63, k-chunk kc), BN+ReLU fused
        for (int i = tid; i < 64 * 16; i += 256) {
            int r = i >> 4, c4 = i & 15;
            int gr = row0 + r;
            float4 v = make_float4(0.f, 0.f, 0.f, 0.f);
            if (gr < n) v = X4[(size_t)gr * 32 + kc * 16 + c4];
            if (use_bn) {
                float4 sc = ((const float4*)g_scale)[kc * 16 + c4];
                float4 sh = ((const float4*)g_shift)[kc * 16 + c4];
                v.x = fmaxf(fmaf(v.x, sc.x, sh.x), 0.f);
                v.y = fmaxf(fmaf(v.y, sc.y, sh.y), 0.f);
                v.z = fmaxf(fmaf(v.z, sc.z, sh.z), 0.f);
                v.w = fmaxf(fmaf(v.w, sc.w, sh.w), 0.f);
            }
            sX4[i] = v;
        }
        __syncthreads();

        #pragma unroll 4
        for (int k4 = 0; k4 < 16; k4++) {
            float4 w0 = sW4[(k4 * 4 + 0) * 32 + lane];
            float4 w1 = sW4[(k4 * 4 + 1) * 32 + lane];
            float4 w2 = sW4[(k4 * 4 + 2) * 32 + lane];
            float4 w3 = sW4[(k4 * 4 + 3) * 32 + lane];
            #pragma unroll
            for (int r = 0; r < 8; r++) {
                float4 xv = sX4[(warp * 8 + r) * 16 + k4];
                acc[r].x += xv.x * w0.x + xv.y * w1.x + xv.z * w2.x + xv.w * w3.x;
                acc[r].y += xv.x * w0.y + xv.y * w1.y + xv.z * w2.y + xv.w * w3.y;
                acc[r].z += xv.x * w0.z + xv.y * w1.z + xv.z * w2.z + xv.w * w3.z;
                acc[r].w += xv.x * w0.w + xv.y * w1.w + xv.z * w2.w + xv.w * w3.w;
            }
        }
        __syncthreads();
    }

    float4 as4 = ((const float4*)avs)[lane];
    float4 ad4 = ((const float4*)avd)[lane];
    #pragma unroll
    for (int r = 0; r < 8; r++) {
        int gr = row0 + warp * 8 + r;
        float ps = acc[r].x * as4.x + acc[r].y * as4.y + acc[r].z * as4.z + acc[r].w * as4.w;
        float pd = acc[r].x * ad4.x + acc[r].y * ad4.y + acc[r].z * ad4.z + acc[r].w * ad4.w;
        #pragma unroll
        for (int o = 16; o > 0; o >>= 1) {
            ps += __shfl_xor_sync(0xffffffffu, ps, o);
            pd += __shfl_xor_sync(0xffffffffu, pd, o);
        }
        if (gr < n) {
            ((float4*)(g_h + (size_t)gr * D))[lane] = acc[r];
            if (lane == 0) { g_as[gr] = ps; g_ad[gr] = pd; }
        }
    }
}

// ---------------- aggregation: warp per dst node, softmax over incoming edges ----------------
__global__ void __launch_bounds__(256)
agg_kernel(const float* __restrict__ bias, float* __restrict__ outext,
           int use_ext, int do_bn, int n) {
    __shared__ float sb_sum[D];
    __shared__ float sb_sq[D];
    if (do_bn) {
        if (threadIdx.x < D) { sb_sum[threadIdx.x] = 0.f; sb_sq[threadIdx.x] = 0.f; }
        __syncthreads();
    }
    int warp = threadIdx.x >> 5, lane = threadIdx.x & 31;
    int node = blockIdx.x * 8 + warp;
    float4 res = make_float4(0.f, 0.f, 0.f, 0.f);
    float* out = use_ext ? outext : g_x;

    if (node < n) {
        int beg = g_rowptr[node], end = g_rowptr[node + 1];
        float md = g_ad[node];
        // phase 1: segment max (edges strided across lanes)
        float m = -3.0e38f;
        for (int j = beg + lane; j < end; j += 32) {
            float e = g_as[g_csr_src[j]] + md;
            e = e > 0.f ? e : 0.2f * e;
            m = fmaxf(m, e);
        }
        #pragma unroll
        for (int o = 16; o > 0; o >>= 1) m = fmaxf(m, __shfl_xor_sync(0xffffffffu, m, o));
        // phase 2: cooperative per-edge weighted accumulation, 2x unrolled for MLP
        float4 a0 = make_float4(0.f, 0.f, 0.f, 0.f);
        float4 a1 = make_float4(0.f, 0.f, 0.f, 0.f);
        float ssum = 0.f;
        int j = beg;
        const float* hb = g_h;
        for (; j + 2 <= end; j += 2) {
            int s0 = g_csr_src[j], s1 = g_csr_src[j + 1];
            float4 h0 = *(const float4*)(hb + (size_t)s0 * D + lane * 4);
            float4 h1 = *(const float4*)(hb + (size_t)s1 * D + lane * 4);
            float e0 = g_as[s0] + md; e0 = e0 > 0.f ? e0 : 0.2f * e0;
            float e1 = g_as[s1] + md; e1 = e1 > 0.f ? e1 : 0.2f * e1;
            float w0 = __expf(e0 - m), w1 = __expf(e1 - m);
            ssum += w0 + w1;
            a0.x += h0.x * w0; a0.y += h0.y * w0; a0.z += h0.z * w0; a0.w += h0.w * w0;
            a1.x += h1.x * w1; a1.y += h1.y * w1; a1.z += h1.z * w1; a1.w += h1.w * w1;
        }
        if (j < end) {
            int s0 = g_csr_src[j];
            float4 h0 = *(const float4*)(hb + (size_t)s0 * D + lane * 4);
            float e0 = g_as[s0] + md; e0 = e0 > 0.f ? e0 : 0.2f * e0;
            float w0 = __expf(e0 - m);
            ssum += w0;
            a0.x += h0.x * w0; a0.y += h0.y * w0; a0.z += h0.z * w0; a0.w += h0.w * w0;
        }
        float inv = 1.f / (ssum + 1e-16f);
        float4 b4 = ((const float4*)bias)[lane];
        res.x = (a0.x + a1.x) * inv + b4.x;
        res.y = (a0.y + a1.y) * inv + b4.y;
        res.z = (a0.z + a1.z) * inv + b4.z;
        res.w = (a0.w + a1.w) * inv + b4.w;
        *((float4*)(out + (size_t)node * D + lane * 4)) = res;
    }

    if (do_bn) {
        if (node < n) {
            int c = lane * 4;
            atomicAdd(&sb_sum[c + 0], res.x); atomicAdd(&sb_sq[c + 0], res.x * res.x);
            atomicAdd(&sb_sum[c + 1], res.y); atomicAdd(&sb_sq[c + 1], res.y * res.y);
            atomicAdd(&sb_sum[c + 2], res.z); atomicAdd(&sb_sq[c + 2], res.z * res.z);
            atomicAdd(&sb_sum[c + 3], res.w); atomicAdd(&sb_sq[c + 3], res.w * res.w);
        }
        __syncthreads();
        if (threadIdx.x < D) {
            atomicAdd(&g_bnsum[threadIdx.x], sb_sum[threadIdx.x]);
            atomicAdd(&g_bnsq[threadIdx.x], sb_sq[threadIdx.x]);
        }
    }
}

// fold BN stats into per-channel scale/shift; reset accumulators for next layer
__global__ void bn_finalize_kernel(const float* __restrict__ gamma,
                                   const float* __restrict__ beta, float inv_n) {
    int c = threadIdx.x;
    float mean = g_bnsum[c] * inv_n;
    float var = g_bnsq[c] * inv_n - mean * mean;
    float sc = gamma[c] * rsqrtf(var + 1e-5f);
    g_scale[c] = sc;
    g_shift[c] = beta[c] - mean * sc;
    g_bnsum[c] = 0.f;
    g_bnsq[c] = 0.f;
}

// ---------------- launch: pure kernel launches, nothing else ----------------
extern "C" void kernel_launch(void* const* d_in, const int* in_sizes, int n_in,
                              void* d_out, int out_size) {
    const float* x    = (const float*)d_in[0];
    const void*  ei   = d_in[1];
    const float* Ws   = (const float*)d_in[2];   // [3,128,128]
    const float* a_s  = (const float*)d_in[3];   // [3,128]
    const float* a_d  = (const float*)d_in[4];   // [3,128]
    const float* bias = (const float*)d_in[5];   // [3,128]
    const float* gam  = (const float*)d_in[6];   // [2,128]
    const float* bet  = (const float*)d_in[7];   // [2,128]
    float* out = (float*)d_out;

    int n = in_sizes[0] / D;
    int E = in_sizes[1] / 2;

    int nblk = (n + 255) / 256;
    int eblk = (E + 255) / 256;
    int gblk = (n + 63) / 64;
    int ablk = (n + 7) / 8;
    float inv_n = 1.0f / (float)n;

    // CSR build (recomputed every launch: deterministic work)
    zero_kernel<<<nblk, 256>>>(n);
    detect_kernel<<<1, 256>>>((const unsigned*)ei);
    count_kernel<<<eblk, 256>>>(ei, E);
    scan_kernel<<<1, 1024>>>(n);
    scatter_kernel<<<eblk, 256>>>(ei, E);

    // layer 0
    gemm_kernel<<<gblk, 256>>>(x, 1, Ws, a_s, a_d, 0, n);
    agg_kernel<<<ablk, 256>>>(bias, nullptr, 0, 1, n);
    bn_finalize_kernel<<<1, D>>>(gam, bet, inv_n);
    // layer 1 (BN+ReLU of layer-0 output fused into GEMM load)
    gemm_kernel<<<gblk, 256>>>(nullptr, 0, Ws + D * D, a_s + D, a_d + D, 1, n);
    agg_kernel<<<ablk, 256>>>(bias + D, nullptr, 0, 1, n);
    bn_finalize_kernel<<<1, D>>>(gam + D, bet + D, inv_n);
    // layer 2 (writes final embeddings straight to d_out)
    gemm_kernel<<<gblk, 256>>>(nullptr, 0, Ws + 2 * D * D, a_s + 2 * D, a_d + 2 * D, 1, n);
    agg_kernel<<<ablk, 256>>>(bias + 2 * D, out, 1, 0, n);
}

// round 3
// speedup vs baseline: 1.0682x; 1.0682x over previous
#include <cuda_runtime.h>
#include <math.h>
#include <stdint.h>

#define MAXN 100000
#define MAXE 1600000
#define D 128
#define SCAN_CHUNK 4096   // elements per scan block (1024 threads x 4)

// ---------------- device scratch (no allocations allowed) ----------------
__device__ float g_h[(size_t)MAXN * D];   // projected features of current layer
__device__ float g_x[(size_t)MAXN * D];   // layer activations (ping buffer)
__device__ float g_as[MAXN];              // alpha_src per node
__device__ float g_ad[MAXN];              // alpha_dst per node
__device__ int   g_csr_src[MAXE];         // src ids sorted by dst
__device__ int   g_rowptr[MAXN + 1];
__device__ int   g_cursor[MAXN];
__device__ int   g_deg[MAXN];
__device__ int   g_bsum[1024];            // per-chunk partial sums
__device__ int   g_boff[1024];            // per-chunk exclusive offsets
__device__ float g_bnsum[D];
__device__ float g_bnsq[D];
__device__ float g_scale[D];
__device__ float g_shift[D];
__device__ int   g_flag;                  // 1 => edge_index stored as int32

// ---------------- init / dtype detection ----------------
__global__ void zero_kernel(int n) {
    int i = blockIdx.x * blockDim.x + threadIdx.x;
    if (i < n) g_deg[i] = 0;
    if (i < D) { g_bnsum[i] = 0.f; g_bnsq[i] = 0.f; }
}

// edge_index layout detection: if int64 (nonneg < 2^31), every odd 32-bit word
// (high half) is 0. Random int32 node ids make that probability ~0.
__global__ void detect_kernel(const unsigned* __restrict__ ei) {
    __shared__ int found;
    if (threadIdx.x == 0) found = 0;
    __syncthreads();
    unsigned w = ei[2 * threadIdx.x + 1];
    if (w != 0u) found = 1;
    __syncthreads();
    if (threadIdx.x == 0) g_flag = found;   // nonzero odd word => int32
}

__device__ __forceinline__ int load_idx(const void* ei, long long pos) {
    if (g_flag) return ((const int*)ei)[pos];
    return (int)((const long long*)ei)[pos];
}

__global__ void count_kernel(const void* __restrict__ ei, int E) {
    int i = blockIdx.x * blockDim.x + threadIdx.x;
    if (i >= E) return;
    int dst = load_idx(ei, (long long)E + i);
    atomicAdd(&g_deg[dst], 1);
}

// ---- multi-block scan: phase A — per-chunk reduce ----
__global__ void scan_reduce_kernel(int n) {
    __shared__ int wsum[32];
    int tid = threadIdx.x, lane = tid & 31, wid = tid >> 5;
    int base = blockIdx.x * SCAN_CHUNK + tid * 4;
    int s = 0;
    #pragma unroll
    for (int k = 0; k < 4; k++) {
        int idx = base + k;
        if (idx < n) s += g_deg[idx];
    }
    #pragma unroll
    for (int o = 16; o > 0; o >>= 1) s += __shfl_xor_sync(0xffffffffu, s, o);
    if (lane == 0) wsum[wid] = s;
    __syncthreads();
    if (wid == 0) {
        int v = wsum[lane];
        #pragma unroll
        for (int o = 16; o > 0; o >>= 1) v += __shfl_xor_sync(0xffffffffu, v, o);
        if (lane == 0) g_bsum[blockIdx.x] = v;
    }
}

// ---- phase B — scan the partials (single block, nb <= 1024) ----
__global__ void scan_top_kernel(int nb, int n) {
    __shared__ int wsum[32];
    int tid = threadIdx.x, lane = tid & 31, wid = tid >> 5;
    int v = (tid < nb) ? g_bsum[tid] : 0;
    int incl = v;
    #pragma unroll
    for (int o = 1; o < 32; o <<= 1) {
        int t = __shfl_up_sync(0xffffffffu, incl, o);
        if (lane >= o) incl += t;
    }
    if (lane == 31) wsum[wid] = incl;
    __syncthreads();
    if (wid == 0) {
        int s = wsum[lane];
        #pragma unroll
        for (int o = 1; o < 32; o <<= 1) {
            int t = __shfl_up_sync(0xffffffffu, s, o);
            if (lane >= o) s += t;
        }
        wsum[lane] = s;
    }
    __syncthreads();
    int excl = (wid > 0 ? wsum[wid - 1] : 0) + incl - v;
    if (tid < nb) g_boff[tid] = excl;
    if (tid == nb - 1) g_rowptr[n] = excl + v;   // total edge count
}

// ---- phase C — local exclusive scan + offset, write rowptr/cursor ----
__global__ void scan_apply_kernel(int n) {
    __shared__ int wsum[32];
    int tid = threadIdx.x, lane = tid & 31, wid = tid >> 5;
    int base = blockIdx.x * SCAN_CHUNK + tid * 4;
    int v[4];
    int tsum = 0;
    #pragma unroll
    for (int k = 0; k < 4; k++) {
        int idx = base + k;
        v[k] = (idx < n) ? g_deg[idx] : 0;
        tsum += v[k];
    }
    int incl = tsum;
    #pragma unroll
    for (int o = 1; o < 32; o <<= 1) {
        int t = __shfl_up_sync(0xffffffffu, incl, o);
        if (lane >= o) incl += t;
    }
    if (lane == 31) wsum[wid] = incl;
    __syncthreads();
    if (wid == 0) {
        int s = wsum[lane];
        #pragma unroll
        for (int o = 1; o < 32; o <<= 1) {
            int t = __shfl_up_sync(0xffffffffu, s, o);
            if (lane >= o) s += t;
        }
        wsum[lane] = s;
    }
    __syncthreads();
    int run = g_boff[blockIdx.x] + (wid > 0 ? wsum[wid - 1] : 0) + incl - tsum;
    #pragma unroll
    for (int k = 0; k < 4; k++) {
        int idx = base + k;
        if (idx < n) { g_rowptr[idx] = run; g_cursor[idx] = run; }
        run += v[k];
    }
}

__global__ void scatter_kernel(const void* __restrict__ ei, int E) {
    int i = blockIdx.x * blockDim.x + threadIdx.x;
    if (i >= E) return;
    int src = load_idx(ei, i);
    int dst = load_idx(ei, (long long)E + i);
    int pos = atomicAdd(&g_cursor[dst], 1);
    g_csr_src[pos] = src;
}

// ---------------- GEMM: h = f(x) @ W, fused BN+ReLU on load, fused alpha dots ----------------
// block = 64 rows x 128 cols, 256 threads (8 warps x 8 rows each, lane owns 4 cols).
// K processed in two 64-wide chunks: sW 32 KB + sX 16 KB = 48 KB static smem.
__global__ void __launch_bounds__(256)
gemm_kernel(const float* __restrict__ xext, int use_ext,
            const float* __restrict__ W,
            const float* __restrict__ avs, const float* __restrict__ avd,
            int use_bn, int n) {
    __shared__ float4 sW4[64 * 32];   // 32 KB
    __shared__ float4 sX4[64 * 16];   // 16 KB
    const float* xsrc = use_ext ? xext : g_x;
    int tid = threadIdx.x;
    int row0 = blockIdx.x * 64;
    int warp = tid >> 5, lane = tid & 31;

    const float4* W4 = (const float4*)W;
    const float4* X4 = (const float4*)xsrc;

    float4 acc[8];
    #pragma unroll
    for (int r = 0; r < 8; r++) acc[r] = make_float4(0.f, 0.f, 0.f, 0.f);

    #pragma unroll
    for (int kc = 0; kc < 2; kc++) {
        #pragma unroll 4
        for (int i = tid; i < 64 * 32; i += 256) sW4[i] = W4[kc * 64 * 32 + i];
        for (int i = tid; i < 64 * 16; i += 256) {
            int r = i >> 4, c4 = i & 15;
            int gr = row0 + r;
            float4 v = make_float4(0.f, 0.f, 0.f, 0.f);
            if (gr < n) v = X4[(size_t)gr * 32 + kc * 16 + c4];
            if (use_bn) {
                float4 sc = ((const float4*)g_scale)[kc * 16 + c4];
                float4 sh = ((const float4*)g_shift)[kc * 16 + c4];
                v.x = fmaxf(fmaf(v.x, sc.x, sh.x), 0.f);
                v.y = fmaxf(fmaf(v.y, sc.y, sh.y), 0.f);
                v.z = fmaxf(fmaf(v.z, sc.z, sh.z), 0.f);
                v.w = fmaxf(fmaf(v.w, sc.w, sh.w), 0.f);
            }
            sX4[i] = v;
        }
        __syncthreads();

        #pragma unroll 4
        for (int k4 = 0; k4 < 16; k4++) {
            float4 w0 = sW4[(k4 * 4 + 0) * 32 + lane];
            float4 w1 = sW4[(k4 * 4 + 1) * 32 + lane];
            float4 w2 = sW4[(k4 * 4 + 2) * 32 + lane];
            float4 w3 = sW4[(k4 * 4 + 3) * 32 + lane];
            #pragma unroll
            for (int r = 0; r < 8; r++) {
                float4 xv = sX4[(warp * 8 + r) * 16 + k4];
                acc[r].x += xv.x * w0.x + xv.y * w1.x + xv.z * w2.x + xv.w * w3.x;
                acc[r].y += xv.x * w0.y + xv.y * w1.y + xv.z * w2.y + xv.w * w3.y;
                acc[r].z += xv.x * w0.z + xv.y * w1.z + xv.z * w2.z + xv.w * w3.z;
                acc[r].w += xv.x * w0.w + xv.y * w1.w + xv.z * w2.w + xv.w * w3.w;
            }
        }
        __syncthreads();
    }

    float4 as4 = ((const float4*)avs)[lane];
    float4 ad4 = ((const float4*)avd)[lane];
    #pragma unroll
    for (int r = 0; r < 8; r++) {
        int gr = row0 + warp * 8 + r;
        float ps = acc[r].x * as4.x + acc[r].y * as4.y + acc[r].z * as4.z + acc[r].w * as4.w;
        float pd = acc[r].x * ad4.x + acc[r].y * ad4.y + acc[r].z * ad4.z + acc[r].w * ad4.w;
        #pragma unroll
        for (int o = 16; o > 0; o >>= 1) {
            ps += __shfl_xor_sync(0xffffffffu, ps, o);
            pd += __shfl_xor_sync(0xffffffffu, pd, o);
        }
        if (gr < n) {
            ((float4*)(g_h + (size_t)gr * D))[lane] = acc[r];
            if (lane == 0) { g_as[gr] = ps; g_ad[gr] = pd; }
        }
    }
}

// ---------------- aggregation: warp per dst node, softmax over incoming edges ----------------
__global__ void __launch_bounds__(256)
agg_kernel(const float* __restrict__ bias, float* __restrict__ outext,
           int use_ext, int do_bn, int n) {
    __shared__ float sb_sum[D];
    __shared__ float sb_sq[D];
    if (do_bn) {
        if (threadIdx.x < D) { sb_sum[threadIdx.x] = 0.f; sb_sq[threadIdx.x] = 0.f; }
        __syncthreads();
    }
    int warp = threadIdx.x >> 5, lane = threadIdx.x & 31;
    int node = blockIdx.x * 8 + warp;
    float4 res = make_float4(0.f, 0.f, 0.f, 0.f);
    float* out = use_ext ? outext : g_x;

    if (node < n) {
        int beg = g_rowptr[node], end = g_rowptr[node + 1];
        float md = g_ad[node];
        // phase 1: segment max (edges strided across lanes)
        float m = -3.0e38f;
        for (int j = beg + lane; j < end; j += 32) {
            float e = g_as[g_csr_src[j]] + md;
            e = e > 0.f ? e : 0.2f * e;
            m = fmaxf(m, e);
        }
        #pragma unroll
        for (int o = 16; o > 0; o >>= 1) m = fmaxf(m, __shfl_xor_sync(0xffffffffu, m, o));
        // phase 2: 4x unrolled cooperative accumulation (MLP=4 on L2 row fetches)
        float4 a0 = make_float4(0.f, 0.f, 0.f, 0.f);
        float4 a1 = make_float4(0.f, 0.f, 0.f, 0.f);
        float ssum = 0.f;
        int j = beg;
        const float* hb = g_h;
        for (; j + 4 <= end; j += 4) {
            int s0 = g_csr_src[j],     s1 = g_csr_src[j + 1];
            int s2 = g_csr_src[j + 2], s3 = g_csr_src[j + 3];
            float4 h0 = *(const float4*)(hb + (size_t)s0 * D + lane * 4);
            float4 h1 = *(const float4*)(hb + (size_t)s1 * D + lane * 4);
            float4 h2 = *(const float4*)(hb + (size_t)s2 * D + lane * 4);
            float4 h3 = *(const float4*)(hb + (size_t)s3 * D + lane * 4);
            float e0 = g_as[s0] + md; e0 = e0 > 0.f ? e0 : 0.2f * e0;
            float e1 = g_as[s1] + md; e1 = e1 > 0.f ? e1 : 0.2f * e1;
            float e2 = g_as[s2] + md; e2 = e2 > 0.f ? e2 : 0.2f * e2;
            float e3 = g_as[s3] + md; e3 = e3 > 0.f ? e3 : 0.2f * e3;
            float w0 = __expf(e0 - m), w1 = __expf(e1 - m);
            float w2 = __expf(e2 - m), w3 = __expf(e3 - m);
            ssum += (w0 + w1) + (w2 + w3);
            a0.x += h0.x * w0; a0.y += h0.y * w0; a0.z += h0.z * w0; a0.w += h0.w * w0;
            a1.x += h1.x * w1; a1.y += h1.y * w1; a1.z += h1.z * w1; a1.w += h1.w * w1;
            a0.x += h2.x * w2; a0.y += h2.y * w2; a0.z += h2.z * w2; a0.w += h2.w * w2;
            a1.x += h3.x * w3; a1.y += h3.y * w3; a1.z += h3.z * w3; a1.w += h3.w * w3;
        }
        for (; j < end; j++) {
            int s0 = g_csr_src[j];
            float4 h0 = *(const float4*)(hb + (size_t)s0 * D + lane * 4);
            float e0 = g_as[s0] + md; e0 = e0 > 0.f ? e0 : 0.2f * e0;
            float w0 = __expf(e0 - m);
            ssum += w0;
            a0.x += h0.x * w0; a0.y += h0.y * w0; a0.z += h0.z * w0; a0.w += h0.w * w0;
        }
        float inv = 1.f / (ssum + 1e-16f);
        float4 b4 = ((const float4*)bias)[lane];
        res.x = (a0.x + a1.x) * inv + b4.x;
        res.y = (a0.y + a1.y) * inv + b4.y;
        res.z = (a0.z + a1.z) * inv + b4.z;
        res.w = (a0.w + a1.w) * inv + b4.w;
        *((float4*)(out + (size_t)node * D + lane * 4)) = res;
    }

    if (do_bn) {
        if (node < n) {
            int c = lane * 4;
            atomicAdd(&sb_sum[c + 0], res.x); atomicAdd(&sb_sq[c + 0], res.x * res.x);
            atomicAdd(&sb_sum[c + 1], res.y); atomicAdd(&sb_sq[c + 1], res.y * res.y);
            atomicAdd(&sb_sum[c + 2], res.z); atomicAdd(&sb_sq[c + 2], res.z * res.z);
            atomicAdd(&sb_sum[c + 3], res.w); atomicAdd(&sb_sq[c + 3], res.w * res.w);
        }
        __syncthreads();
        if (threadIdx.x < D) {
            atomicAdd(&g_bnsum[threadIdx.x], sb_sum[threadIdx.x]);
            atomicAdd(&g_bnsq[threadIdx.x], sb_sq[threadIdx.x]);
        }
    }
}

// fold BN stats into per-channel scale/shift; reset accumulators for next layer
__global__ void bn_finalize_kernel(const float* __restrict__ gamma,
                                   const float* __restrict__ beta, float inv_n) {
    int c = threadIdx.x;
    float mean = g_bnsum[c] * inv_n;
    float var = g_bnsq[c] * inv_n - mean * mean;
    float sc = gamma[c] * rsqrtf(var + 1e-5f);
    g_scale[c] = sc;
    g_shift[c] = beta[c] - mean * sc;
    g_bnsum[c] = 0.f;
    g_bnsq[c] = 0.f;
}

// ---------------- launch: pure kernel launches, nothing else ----------------
extern "C" void kernel_launch(void* const* d_in, const int* in_sizes, int n_in,
                              void* d_out, int out_size) {
    const float* x    = (const float*)d_in[0];
    const void*  ei   = d_in[1];
    const float* Ws   = (const float*)d_in[2];   // [3,128,128]
    const float* a_s  = (const float*)d_in[3];   // [3,128]
    const float* a_d  = (const float*)d_in[4];   // [3,128]
    const float* bias = (const float*)d_in[5];   // [3,128]
    const float* gam  = (const float*)d_in[6];   // [2,128]
    const float* bet  = (const float*)d_in[7];   // [2,128]
    float* out = (float*)d_out;

    int n = in_sizes[0] / D;
    int E = in_sizes[1] / 2;

    int nblk = (n + 255) / 256;
    int eblk = (E + 255) / 256;
    int gblk = (n + 63) / 64;
    int ablk = (n + 7) / 8;
    int sblk = (n + SCAN_CHUNK - 1) / SCAN_CHUNK;
    float inv_n = 1.0f / (float)n;

    // CSR build
    zero_kernel<<<nblk, 256>>>(n);
    detect_kernel<<<1, 256>>>((const unsigned*)ei);
    count_kernel<<<eblk, 256>>>(ei, E);
    scan_reduce_kernel<<<sblk, 1024>>>(n);
    scan_top_kernel<<<1, 1024>>>(sblk, n);
    scan_apply_kernel<<<sblk, 1024>>>(n);
    scatter_kernel<<<eblk, 256>>>(ei, E);

    // layer 0
    gemm_kernel<<<gblk, 256>>>(x, 1, Ws, a_s, a_d, 0, n);
    agg_kernel<<<ablk, 256>>>(bias, nullptr, 0, 1, n);
    bn_finalize_kernel<<<1, D>>>(gam, bet, inv_n);
    // layer 1 (BN+ReLU of layer-0 output fused into GEMM load)
    gemm_kernel<<<gblk, 256>>>(nullptr, 0, Ws + D * D, a_s + D, a_d + D, 1, n);
    agg_kernel<<<ablk, 256>>>(bias + D, nullptr, 0, 1, n);
    bn_finalize_kernel<<<1, D>>>(gam + D, bet + D, inv_n);
    // layer 2 (writes final embeddings straight to d_out)
    gemm_kernel<<<gblk, 256>>>(nullptr, 0, Ws + 2 * D * D, a_s + 2 * D, a_d + 2 * D, 1, n);
    agg_kernel<<<ablk, 256>>>(bias + 2 * D, out, 1, 0, n);
}

// round 4
// speedup vs baseline: 1.1850x; 1.1094x over previous
#include <cuda_runtime.h>
#include <cuda_fp16.h>
#include <math.h>
#include <stdint.h>

#define MAXN 100000
#define MAXE 1600000
#define D 128
#define SCAN_CHUNK 4096   // elements per scan block (1024 threads x 4)

// ---------------- device scratch (no allocations allowed) ----------------
__device__ uint2 g_hh[(size_t)MAXN * 32]; // projected features, fp16x2 packed (256B/row)
__device__ float g_x[(size_t)MAXN * D];   // layer activations (ping buffer)
__device__ float g_as[MAXN];              // alpha_src per node
__device__ float g_ad[MAXN];              // alpha_dst per node
__device__ int   g_csr_src[MAXE];         // src ids sorted by dst
__device__ int   g_rowptr[MAXN + 1];
__device__ int   g_cursor[MAXN];
__device__ int   g_deg[MAXN];
__device__ int   g_bsum[1024];            // per-chunk partial sums
__device__ int   g_boff[1024];            // per-chunk exclusive offsets
__device__ float g_bnsum[D];
__device__ float g_bnsq[D];
__device__ float g_scale[D];
__device__ float g_shift[D];
__device__ int   g_flag;                  // 1 => edge_index stored as int32

// ---------------- init / dtype detection ----------------
__global__ void zero_kernel(int n) {
    int i = blockIdx.x * blockDim.x + threadIdx.x;
    if (i < n) g_deg[i] = 0;
    if (i < D) { g_bnsum[i] = 0.f; g_bnsq[i] = 0.f; }
}

// edge_index layout detection: if int64 (nonneg < 2^31), every odd 32-bit word
// (high half) is 0. Random int32 node ids make that probability ~0.
__global__ void detect_kernel(const unsigned* __restrict__ ei) {
    __shared__ int found;
    if (threadIdx.x == 0) found = 0;
    __syncthreads();
    unsigned w = ei[2 * threadIdx.x + 1];
    if (w != 0u) found = 1;
    __syncthreads();
    if (threadIdx.x == 0) g_flag = found;   // nonzero odd word => int32
}

__device__ __forceinline__ int load_idx(const void* ei, long long pos) {
    if (g_flag) return ((const int*)ei)[pos];
    return (int)((const long long*)ei)[pos];
}

__global__ void count_kernel(const void* __restrict__ ei, int E) {
    int i = blockIdx.x * blockDim.x + threadIdx.x;
    if (i >= E) return;
    int dst = load_idx(ei, (long long)E + i);
    atomicAdd(&g_deg[dst], 1);
}

// ---- multi-block scan: phase A — per-chunk reduce ----
__global__ void scan_reduce_kernel(int n) {
    __shared__ int wsum[32];
    int tid = threadIdx.x, lane = tid & 31, wid = tid >> 5;
    int base = blockIdx.x * SCAN_CHUNK + tid * 4;
    int s = 0;
    #pragma unroll
    for (int k = 0; k < 4; k++) {
        int idx = base + k;
        if (idx < n) s += g_deg[idx];
    }
    #pragma unroll
    for (int o = 16; o > 0; o >>= 1) s += __shfl_xor_sync(0xffffffffu, s, o);
    if (lane == 0) wsum[wid] = s;
    __syncthreads();
    if (wid == 0) {
        int v = wsum[lane];
        #pragma unroll
        for (int o = 16; o > 0; o >>= 1) v += __shfl_xor_sync(0xffffffffu, v, o);
        if (lane == 0) g_bsum[blockIdx.x] = v;
    }
}

// ---- phase B — scan the partials (single block, nb <= 1024) ----
__global__ void scan_top_kernel(int nb, int n) {
    __shared__ int wsum[32];
    int tid = threadIdx.x, lane = tid & 31, wid = tid >> 5;
    int v = (tid < nb) ? g_bsum[tid] : 0;
    int incl = v;
    #pragma unroll
    for (int o = 1; o < 32; o <<= 1) {
        int t = __shfl_up_sync(0xffffffffu, incl, o);
        if (lane >= o) incl += t;
    }
    if (lane == 31) wsum[wid] = incl;
    __syncthreads();
    if (wid == 0) {
        int s = wsum[lane];
        #pragma unroll
        for (int o = 1; o < 32; o <<= 1) {
            int t = __shfl_up_sync(0xffffffffu, s, o);
            if (lane >= o) s += t;
        }
        wsum[lane] = s;
    }
    __syncthreads();
    int excl = (wid > 0 ? wsum[wid - 1] : 0) + incl - v;
    if (tid < nb) g_boff[tid] = excl;
    if (tid == nb - 1) g_rowptr[n] = excl + v;   // total edge count
}

// ---- phase C — local exclusive scan + offset, write rowptr/cursor ----
__global__ void scan_apply_kernel(int n) {
    __shared__ int wsum[32];
    int tid = threadIdx.x, lane = tid & 31, wid = tid >> 5;
    int base = blockIdx.x * SCAN_CHUNK + tid * 4;
    int v[4];
    int tsum = 0;
    #pragma unroll
    for (int k = 0; k < 4; k++) {
        int idx = base + k;
        v[k] = (idx < n) ? g_deg[idx] : 0;
        tsum += v[k];
    }
    int incl = tsum;
    #pragma unroll
    for (int o = 1; o < 32; o <<= 1) {
        int t = __shfl_up_sync(0xffffffffu, incl, o);
        if (lane >= o) incl += t;
    }
    if (lane == 31) wsum[wid] = incl;
    __syncthreads();
    if (wid == 0) {
        int s = wsum[lane];
        #pragma unroll
        for (int o = 1; o < 32; o <<= 1) {
            int t = __shfl_up_sync(0xffffffffu, s, o);
            if (lane >= o) s += t;
        }
        wsum[lane] = s;
    }
    __syncthreads();
    int run = g_boff[blockIdx.x] + (wid > 0 ? wsum[wid - 1] : 0) + incl - tsum;
    #pragma unroll
    for (int k = 0; k < 4; k++) {
        int idx = base + k;
        if (idx < n) { g_rowptr[idx] = run; g_cursor[idx] = run; }
        run += v[k];
    }
}

__global__ void scatter_kernel(const void* __restrict__ ei, int E) {
    int i = blockIdx.x * blockDim.x + threadIdx.x;
    if (i >= E) return;
    int src = load_idx(ei, i);
    int dst = load_idx(ei, (long long)E + i);
    int pos = atomicAdd(&g_cursor[dst], 1);
    g_csr_src[pos] = src;
}

// ---------------- GEMM: h = f(x) @ W via packed fp32x2 FMA (FFMA2) ----------------
// block = 64 rows x 128 cols, 256 threads (8 warps x 8 rows each, lane owns 4 cols).
// K processed in two 64-wide chunks: sW 32 KB + sX 16 KB = 48 KB static smem.
// Accumulators are column-pairs packed in 64-bit regs; inner loop issues
// fma.rn.f32x2 (exact fp32 math, 2 MACs/instr).
#define DUP_F32X2(dst, srcu) \
    asm("mov.b64 %0, {%1, %1};" : "=l"(dst) : "r"(srcu))
#define FMA_F32X2(acc, a, b) \
    asm("fma.rn.f32x2 %0, %1, %2, %0;" : "+l"(acc) : "l"(a), "l"(b))

__global__ void __launch_bounds__(256)
gemm_kernel(const float* __restrict__ xext, int use_ext,
            const float* __restrict__ W,
            const float* __restrict__ avs, const float* __restrict__ avd,
            int use_bn, int n) {
    __shared__ float4 sW4[64 * 32];   // 32 KB
    __shared__ float4 sX4[64 * 16];   // 16 KB
    const float* xsrc = use_ext ? xext : g_x;
    int tid = threadIdx.x;
    int row0 = blockIdx.x * 64;
    int warp = tid >> 5, lane = tid & 31;

    const float4* W4 = (const float4*)W;
    const float4* X4 = (const float4*)xsrc;

    unsigned long long accl[8], acch[8];   // packed (c0,c1) / (c2,c3)
    #pragma unroll
    for (int r = 0; r < 8; r++) { accl[r] = 0ull; acch[r] = 0ull; }

    #pragma unroll
    for (int kc = 0; kc < 2; kc++) {
        #pragma unroll 4
        for (int i = tid; i < 64 * 32; i += 256) sW4[i] = W4[kc * 64 * 32 + i];
        for (int i = tid; i < 64 * 16; i += 256) {
            int r = i >> 4, c4 = i & 15;
            int gr = row0 + r;
            float4 v = make_float4(0.f, 0.f, 0.f, 0.f);
            if (gr < n) v = X4[(size_t)gr * 32 + kc * 16 + c4];
            if (use_bn) {
                float4 sc = ((const float4*)g_scale)[kc * 16 + c4];
                float4 sh = ((const float4*)g_shift)[kc * 16 + c4];
                v.x = fmaxf(fmaf(v.x, sc.x, sh.x), 0.f);
                v.y = fmaxf(fmaf(v.y, sc.y, sh.y), 0.f);
                v.z = fmaxf(fmaf(v.z, sc.z, sh.z), 0.f);
                v.w = fmaxf(fmaf(v.w, sc.w, sh.w), 0.f);
            }
            sX4[i] = v;
        }
        __syncthreads();

        const unsigned long long* sW8 = (const unsigned long long*)sW4;
        #pragma unroll 2
        for (int k4 = 0; k4 < 16; k4++) {
            unsigned long long wl[4], wh[4];
            #pragma unroll
            for (int kk = 0; kk < 4; kk++) {
                int off = ((k4 * 4 + kk) * 32 + lane) * 2;
                wl[kk] = sW8[off];
                wh[kk] = sW8[off + 1];
            }
            #pragma unroll
            for (int r = 0; r < 8; r++) {
                float4 xv = sX4[(warp * 8 + r) * 16 + k4];
                unsigned long long xx;
                DUP_F32X2(xx, __float_as_uint(xv.x));
                FMA_F32X2(accl[r], xx, wl[0]);
                FMA_F32X2(acch[r], xx, wh[0]);
                DUP_F32X2(xx, __float_as_uint(xv.y));
                FMA_F32X2(accl[r], xx, wl[1]);
                FMA_F32X2(acch[r], xx, wh[1]);
                DUP_F32X2(xx, __float_as_uint(xv.z));
                FMA_F32X2(accl[r], xx, wl[2]);
                FMA_F32X2(acch[r], xx, wh[2]);
                DUP_F32X2(xx, __float_as_uint(xv.w));
                FMA_F32X2(accl[r], xx, wl[3]);
                FMA_F32X2(acch[r], xx, wh[3]);
            }
        }
        __syncthreads();
    }

    float4 as4 = ((const float4*)avs)[lane];
    float4 ad4 = ((const float4*)avd)[lane];
    #pragma unroll
    for (int r = 0; r < 8; r++) {
        int gr = row0 + warp * 8 + r;
        unsigned u0, u1, u2, u3;
        asm("mov.b64 {%0, %1}, %2;" : "=r"(u0), "=r"(u1) : "l"(accl[r]));
        asm("mov.b64 {%0, %1}, %2;" : "=r"(u2), "=r"(u3) : "l"(acch[r]));
        float4 a4 = make_float4(__uint_as_float(u0), __uint_as_float(u1),
                                __uint_as_float(u2), __uint_as_float(u3));
        float ps = a4.x * as4.x + a4.y * as4.y + a4.z * as4.z + a4.w * as4.w;
        float pd = a4.x * ad4.x + a4.y * ad4.y + a4.z * ad4.z + a4.w * ad4.w;
        #pragma unroll
        for (int o = 16; o > 0; o >>= 1) {
            ps += __shfl_xor_sync(0xffffffffu, ps, o);
            pd += __shfl_xor_sync(0xffffffffu, pd, o);
        }
        if (gr < n) {
            __half2 p0 = __floats2half2_rn(a4.x, a4.y);
            __half2 p1 = __floats2half2_rn(a4.z, a4.w);
            uint2 pk;
            pk.x = *(unsigned*)&p0;
            pk.y = *(unsigned*)&p1;
            g_hh[(size_t)gr * 32 + lane] = pk;
            if (lane == 0) { g_as[gr] = ps; g_ad[gr] = pd; }
        }
    }
}

// ---------------- aggregation: warp per dst node, softmax over incoming edges ----------------
__global__ void __launch_bounds__(256)
agg_kernel(const float* __restrict__ bias, float* __restrict__ outext,
           int use_ext, int do_bn, int n) {
    __shared__ float sb_sum[D];
    __shared__ float sb_sq[D];
    if (do_bn) {
        if (threadIdx.x < D) { sb_sum[threadIdx.x] = 0.f; sb_sq[threadIdx.x] = 0.f; }
        __syncthreads();
    }
    int warp = threadIdx.x >> 5, lane = threadIdx.x & 31;
    int node = blockIdx.x * 8 + warp;
    float4 res = make_float4(0.f, 0.f, 0.f, 0.f);
    float* out = use_ext ? outext : g_x;

    if (node < n) {
        int beg = g_rowptr[node], end = g_rowptr[node + 1];
        float md = g_ad[node];
        // phase 1: segment max (edges strided across lanes)
        float m = -3.0e38f;
        for (int j = beg + lane; j < end; j += 32) {
            float e = g_as[g_csr_src[j]] + md;
            e = e > 0.f ? e : 0.2f * e;
            m = fmaxf(m, e);
        }
        #pragma unroll
        for (int o = 16; o > 0; o >>= 1) m = fmaxf(m, __shfl_xor_sync(0xffffffffu, m, o));
        // phase 2: 4x unrolled cooperative accumulation over fp16-packed h rows
        float4 a0 = make_float4(0.f, 0.f, 0.f, 0.f);
        float4 a1 = make_float4(0.f, 0.f, 0.f, 0.f);
        float ssum = 0.f;
        int j = beg;
        const uint2* hb = g_hh;
        for (; j + 4 <= end; j += 4) {
            int s0 = g_csr_src[j],     s1 = g_csr_src[j + 1];
            int s2 = g_csr_src[j + 2], s3 = g_csr_src[j + 3];
            uint2 p0 = hb[(size_t)s0 * 32 + lane];
            uint2 p1 = hb[(size_t)s1 * 32 + lane];
            uint2 p2 = hb[(size_t)s2 * 32 + lane];
            uint2 p3 = hb[(size_t)s3 * 32 + lane];
            float e0 = g_as[s0] + md; e0 = e0 > 0.f ? e0 : 0.2f * e0;
            float e1 = g_as[s1] + md; e1 = e1 > 0.f ? e1 : 0.2f * e1;
            float e2 = g_as[s2] + md; e2 = e2 > 0.f ? e2 : 0.2f * e2;
            float e3 = g_as[s3] + md; e3 = e3 > 0.f ? e3 : 0.2f * e3;
            float w0 = __expf(e0 - m), w1 = __expf(e1 - m);
            float w2 = __expf(e2 - m), w3 = __expf(e3 - m);
            ssum += (w0 + w1) + (w2 + w3);
            float2 f;
            f = __half22float2(*(__half2*)&p0.x); a0.x += f.x * w0; a0.y += f.y * w0;
            f = __half22float2(*(__half2*)&p0.y); a0.z += f.x * w0; a0.w += f.y * w0;
            f = __half22float2(*(__half2*)&p1.x); a1.x += f.x * w1; a1.y += f.y * w1;
            f = __half22float2(*(__half2*)&p1.y); a1.z += f.x * w1; a1.w += f.y * w1;
            f = __half22float2(*(__half2*)&p2.x); a0.x += f.x * w2; a0.y += f.y * w2;
            f = __half22float2(*(__half2*)&p2.y); a0.z += f.x * w2; a0.w += f.y * w2;
            f = __half22float2(*(__half2*)&p3.x); a1.x += f.x * w3; a1.y += f.y * w3;
            f = __half22float2(*(__half2*)&p3.y); a1.z += f.x * w3; a1.w += f.y * w3;
        }
        for (; j < end; j++) {
            int s0 = g_csr_src[j];
            uint2 p0 = hb[(size_t)s0 * 32 + lane];
            float e0 = g_as[s0] + md; e0 = e0 > 0.f ? e0 : 0.2f * e0;
            float w0 = __expf(e0 - m);
            ssum += w0;
            float2 f;
            f = __half22float2(*(__half2*)&p0.x); a0.x += f.x * w0; a0.y += f.y * w0;
            f = __half22float2(*(__half2*)&p0.y); a0.z += f.x * w0; a0.w += f.y * w0;
        }
        float inv = 1.f / (ssum + 1e-16f);
        float4 b4 = ((const float4*)bias)[lane];
        res.x = (a0.x + a1.x) * inv + b4.x;
        res.y = (a0.y + a1.y) * inv + b4.y;
        res.z = (a0.z + a1.z) * inv + b4.z;
        res.w = (a0.w + a1.w) * inv + b4.w;
        *((float4*)(out + (size_t)node * D + lane * 4)) = res;
    }

    if (do_bn) {
        if (node < n) {
            int c = lane * 4;
            atomicAdd(&sb_sum[c + 0], res.x); atomicAdd(&sb_sq[c + 0], res.x * res.x);
            atomicAdd(&sb_sum[c + 1], res.y); atomicAdd(&sb_sq[c + 1], res.y * res.y);
            atomicAdd(&sb_sum[c + 2], res.z); atomicAdd(&sb_sq[c + 2], res.z * res.z);
            atomicAdd(&sb_sum[c + 3], res.w); atomicAdd(&sb_sq[c + 3], res.w * res.w);
        }
        __syncthreads();
        if (threadIdx.x < D) {
            atomicAdd(&g_bnsum[threadIdx.x], sb_sum[threadIdx.x]);
            atomicAdd(&g_bnsq[threadIdx.x], sb_sq[threadIdx.x]);
        }
    }
}

// fold BN stats into per-channel scale/shift; reset accumulators for next layer
__global__ void bn_finalize_kernel(const float* __restrict__ gamma,
                                   const float* __restrict__ beta, float inv_n) {
    int c = threadIdx.x;
    float mean = g_bnsum[c] * inv_n;
    float var = g_bnsq[c] * inv_n - mean * mean;
    float sc = gamma[c] * rsqrtf(var + 1e-5f);
    g_scale[c] = sc;
    g_shift[c] = beta[c] - mean * sc;
    g_bnsum[c] = 0.f;
    g_bnsq[c] = 0.f;
}

// ---------------- launch: pure kernel launches, nothing else ----------------
extern "C" void kernel_launch(void* const* d_in, const int* in_sizes, int n_in,
                              void* d_out, int out_size) {
    const float* x    = (const float*)d_in[0];
    const void*  ei   = d_in[1];
    const float* Ws   = (const float*)d_in[2];   // [3,128,128]
    const float* a_s  = (const float*)d_in[3];   // [3,128]
    const float* a_d  = (const float*)d_in[4];   // [3,128]
    const float* bias = (const float*)d_in[5];   // [3,128]
    const float* gam  = (const float*)d_in[6];   // [2,128]
    const float* bet  = (const float*)d_in[7];   // [2,128]
    float* out = (float*)d_out;

    int n = in_sizes[0] / D;
    int E = in_sizes[1] / 2;

    int nblk = (n + 255) / 256;
    int eblk = (E + 255) / 256;
    int gblk = (n + 63) / 64;
    int ablk = (n + 7) / 8;
    int sblk = (n + SCAN_CHUNK - 1) / SCAN_CHUNK;
    float inv_n = 1.0f / (float)n;

    // CSR build
    zero_kernel<<<nblk, 256>>>(n);
    detect_kernel<<<1, 256>>>((const unsigned*)ei);
    count_kernel<<<eblk, 256>>>(ei, E);
    scan_reduce_kernel<<<sblk, 1024>>>(n);
    scan_top_kernel<<<1, 1024>>>(sblk, n);
    scan_apply_kernel<<<sblk, 1024>>>(n);
    scatter_kernel<<<eblk, 256>>>(ei, E);

    // layer 0
    gemm_kernel<<<gblk, 256>>>(x, 1, Ws, a_s, a_d, 0, n);
    agg_kernel<<<ablk, 256>>>(bias, nullptr, 0, 1, n);
    bn_finalize_kernel<<<1, D>>>(gam, bet, inv_n);
    // layer 1 (BN+ReLU of layer-0 output fused into GEMM load)
    gemm_kernel<<<gblk, 256>>>(nullptr, 0, Ws + D * D, a_s + D, a_d + D, 1, n);
    agg_kernel<<<ablk, 256>>>(bias + D, nullptr, 0, 1, n);
    bn_finalize_kernel<<<1, D>>>(gam + D, bet + D, inv_n);
    // layer 2 (writes final embeddings straight to d_out)
    gemm_kernel<<<gblk, 256>>>(nullptr, 0, Ws + 2 * D * D, a_s + 2 * D, a_d + 2 * D, 1, n);
    agg_kernel<<<ablk, 256>>>(bias + 2 * D, out, 1, 0, n);
}